// round 9
// baseline (speedup 1.0000x reference)
#include <cuda_runtime.h>
#include <cuda_bf16.h>
#include <stdint.h>

// GCN mean aggregation:
//   out[i, :] = mean over {nodes[i]} ∪ neigh_idx[i,0..31] of features[idx, :]
// features [V=100000, D=128] f32, nodes [B] int{32|64}, neigh [B,32] int{32|64}.
//
// Warp per node, single-line LDG.32 gather (one 128B line per instruction).
// NEW: traffic split across memory levels. The L2 hit path plateaus at
// ~18.6 TB/s while DRAM idles, so the table is partitioned by row index:
//   rows <  T (80%): evict_last  -> resident, served by L2     (~676 MB)
//   rows >= T (20%): evict_first -> evicted fast, served by HBM (~169 MB)
// Aggregate BW = L2 + DRAM instead of L2 alone.
//  - index loads / output stores: streaming (.cs)
//  - index dtype (int64 vs JAX-demoted int32) probed inline per warp.

static constexpr int KN = 32;
static constexpr float INV_CNT = 1.0f / 33.0f;
static constexpr int   T_SPLIT = 80000;   // rows below: L2 class; above: DRAM class

__device__ __forceinline__ uint64_t make_keep_policy() {
    uint64_t pol;
    asm("createpolicy.fractional.L2::evict_last.b64 %0, 1.0;" : "=l"(pol));
    return pol;
}

__device__ __forceinline__ uint64_t make_stream_policy() {
    uint64_t pol;
    asm("createpolicy.fractional.L2::evict_first.b64 %0, 1.0;" : "=l"(pol));
    return pol;
}

__device__ __forceinline__ float ldg_pol(const float* p, uint64_t pol) {
    float v;
    asm volatile("ld.global.nc.L2::cache_hint.f32 %0, [%1], %2;"
                 : "=f"(v) : "l"(p), "l"(pol));
    return v;
}

__device__ __forceinline__ void stg_stream1(float* p, float v) {
    asm volatile("st.global.cs.f32 [%0], %1;" :: "l"(p), "f"(v) : "memory");
}

__device__ __forceinline__ int2 ldg_cs32x2(const int* p) {
    int2 v;
    asm volatile("ld.global.cs.v2.s32 {%0,%1}, [%2];"
                 : "=r"(v.x), "=r"(v.y) : "l"(p));
    return v;
}

__device__ __forceinline__ long long ldg_cs64(const long long* p) {
    long long v;
    asm volatile("ld.global.cs.s64 %0, [%1];" : "=l"(v) : "l"(p));
    return v;
}

__device__ __forceinline__ int ldg_cs32(const int* p) {
    int v;
    asm volatile("ld.global.cs.s32 %0, [%1];" : "=r"(v) : "l"(p));
    return v;
}

__global__ __launch_bounds__(256) void gcn_agg_kernel(
    const float* __restrict__ feat,
    const void*  __restrict__ nodes,
    const void*  __restrict__ neigh,
    float*       __restrict__ out,
    int B)
{
    const int node = (blockIdx.x * blockDim.x + threadIdx.x) >> 5;
    const int lane = threadIdx.x & 31;
    if (node >= B) return;

    // Inline index-dtype detection: little-endian int64 values < 2^31 have
    // every odd 32-bit word zero (probe first 64 words of neigh).
    const int2 probe = ldg_cs32x2((const int*)neigh + 2 * lane);
    const bool is64 = (__ballot_sync(0xffffffffu, probe.y == 0) == 0xffffffffu);

    // Fetch this node's indices: lane j holds neighbor j (coalesced).
    int my_idx, self_idx;
    if (is64) {
        my_idx   = (int)ldg_cs64((const long long*)neigh + (long long)node * KN + lane);
        self_idx = (int)ldg_cs64((const long long*)nodes + node);
    } else {
        my_idx   = ldg_cs32((const int*)neigh + (long long)node * KN + lane);
        self_idx = ldg_cs32((const int*)nodes + node);
    }

    const uint64_t polK = make_keep_policy();
    const uint64_t polS = make_stream_policy();

    float acc0, acc1, acc2, acc3;
    {
        const uint64_t p = (self_idx < T_SPLIT) ? polK : polS;
        const float* r = feat + (long long)self_idx * 128 + lane;
        acc0 = ldg_pol(r,      p);
        acc1 = ldg_pol(r + 32, p);
        acc2 = ldg_pol(r + 64, p);
        acc3 = ldg_pol(r + 96, p);
    }
#pragma unroll
    for (int j = 0; j < KN; j++) {
        const int idx = __shfl_sync(0xffffffffu, my_idx, j);
        const uint64_t p = (idx < T_SPLIT) ? polK : polS;   // uniform per warp
        const float* r = feat + (long long)idx * 128 + lane;
        acc0 += ldg_pol(r,      p);
        acc1 += ldg_pol(r + 32, p);
        acc2 += ldg_pol(r + 64, p);
        acc3 += ldg_pol(r + 96, p);
    }

    float* op = out + (long long)node * 128 + lane;
    stg_stream1(op,      acc0 * INV_CNT);
    stg_stream1(op + 32, acc1 * INV_CNT);
    stg_stream1(op + 64, acc2 * INV_CNT);
    stg_stream1(op + 96, acc3 * INV_CNT);
}

extern "C" void kernel_launch(void* const* d_in, const int* in_sizes, int n_in,
                              void* d_out, int out_size) {
    const float* feat  = (const float*)d_in[0];
    const void*  nodes = d_in[1];
    const void*  neigh = d_in[2];
    float*       out   = (float*)d_out;

    const int B = in_sizes[1];  // 50000

    const int threads = 256;   // 8 warps = 8 nodes per block
    const int blocks  = (B * 32 + threads - 1) / threads;
    gcn_agg_kernel<<<blocks, threads>>>(feat, nodes, neigh, out, B);
}

// round 10
// speedup vs baseline: 1.0067x; 1.0067x over previous
#include <cuda_runtime.h>
#include <cuda_bf16.h>
#include <stdint.h>

// GCN mean aggregation (FINAL — at the L2 random-gather bandwidth wall):
//   out[i, :] = mean over {nodes[i]} ∪ neigh_idx[i,0..31] of features[idx, :]
// features [V=100000, D=128] f32, nodes [B] int{32|64}, neigh [B,32] int{32|64}.
//
// Converged design, validated over 7 structural variants (all 47.6-52us):
//  - warp per node; lane loads 4B -> each LDG touches exactly one 128B line,
//    4 loads per 512B feature row, fully coalesced
//  - feature loads: .nc + L2::evict_last policy. This was the one big win
//    (80.9 -> 47.6us): keeps the 51.2MB table resident in L2 instead of
//    letting write-once output/index streams evict it
//  - index loads / output stores: streaming (.cs) so they never claim L2
//  - indices fetched coalesced (lane j = neighbor j) + shfl broadcast
//  - index dtype (int64 vs JAX-demoted int32) probed inline per warp:
//    little-endian int64 values < 2^31 have every odd 32-bit word zero
// Warm delivery = 884MB / 47.6us ~= 18.6 TB/s through the LTS, invariant to
// LDG width, MLP, occupancy, L1 bypass, and L2/DRAM traffic splits -> this is
// the chip's L2-hit gather ceiling; traffic itself is irreducible (uniform
// random indices, ~1% inter-node overlap, no exploitable reuse above L2).

static constexpr int KN = 32;
static constexpr float INV_CNT = 1.0f / 33.0f;

__device__ __forceinline__ uint64_t make_keep_policy() {
    uint64_t pol;
    asm("createpolicy.fractional.L2::evict_last.b64 %0, 1.0;" : "=l"(pol));
    return pol;
}

__device__ __forceinline__ float ldg_keep1(const float* p, uint64_t pol) {
    float v;
    asm volatile("ld.global.nc.L2::cache_hint.f32 %0, [%1], %2;"
                 : "=f"(v) : "l"(p), "l"(pol));
    return v;
}

__device__ __forceinline__ void stg_stream1(float* p, float v) {
    asm volatile("st.global.cs.f32 [%0], %1;" :: "l"(p), "f"(v) : "memory");
}

__device__ __forceinline__ int2 ldg_cs32x2(const int* p) {
    int2 v;
    asm volatile("ld.global.cs.v2.s32 {%0,%1}, [%2];"
                 : "=r"(v.x), "=r"(v.y) : "l"(p));
    return v;
}

__device__ __forceinline__ long long ldg_cs64(const long long* p) {
    long long v;
    asm volatile("ld.global.cs.s64 %0, [%1];" : "=l"(v) : "l"(p));
    return v;
}

__device__ __forceinline__ int ldg_cs32(const int* p) {
    int v;
    asm volatile("ld.global.cs.s32 %0, [%1];" : "=r"(v) : "l"(p));
    return v;
}

__global__ __launch_bounds__(256) void gcn_agg_kernel(
    const float* __restrict__ feat,
    const void*  __restrict__ nodes,
    const void*  __restrict__ neigh,
    float*       __restrict__ out,
    int B)
{
    const int node = (blockIdx.x * blockDim.x + threadIdx.x) >> 5;
    const int lane = threadIdx.x & 31;
    if (node >= B) return;

    // Inline index-dtype detection (probe first 64 words of neigh).
    const int2 probe = ldg_cs32x2((const int*)neigh + 2 * lane);
    const bool is64 = (__ballot_sync(0xffffffffu, probe.y == 0) == 0xffffffffu);

    // Fetch this node's indices: lane j holds neighbor j (coalesced).
    int my_idx, self_idx;
    if (is64) {
        my_idx   = (int)ldg_cs64((const long long*)neigh + (long long)node * KN + lane);
        self_idx = (int)ldg_cs64((const long long*)nodes + node);
    } else {
        my_idx   = ldg_cs32((const int*)neigh + (long long)node * KN + lane);
        self_idx = ldg_cs32((const int*)nodes + node);
    }

    const uint64_t pol = make_keep_policy();

    // Gather: 4 single-line LDG.32 per 512B row.
    float acc0, acc1, acc2, acc3;
    {
        const float* r = feat + (long long)self_idx * 128 + lane;
        acc0 = ldg_keep1(r,      pol);
        acc1 = ldg_keep1(r + 32, pol);
        acc2 = ldg_keep1(r + 64, pol);
        acc3 = ldg_keep1(r + 96, pol);
    }
#pragma unroll
    for (int j = 0; j < KN; j++) {
        const int idx = __shfl_sync(0xffffffffu, my_idx, j);
        const float* r = feat + (long long)idx * 128 + lane;
        acc0 += ldg_keep1(r,      pol);
        acc1 += ldg_keep1(r + 32, pol);
        acc2 += ldg_keep1(r + 64, pol);
        acc3 += ldg_keep1(r + 96, pol);
    }

    float* op = out + (long long)node * 128 + lane;
    stg_stream1(op,      acc0 * INV_CNT);
    stg_stream1(op + 32, acc1 * INV_CNT);
    stg_stream1(op + 64, acc2 * INV_CNT);
    stg_stream1(op + 96, acc3 * INV_CNT);
}

extern "C" void kernel_launch(void* const* d_in, const int* in_sizes, int n_in,
                              void* d_out, int out_size) {
    const float* feat  = (const float*)d_in[0];
    const void*  nodes = d_in[1];
    const void*  neigh = d_in[2];
    float*       out   = (float*)d_out;

    const int B = in_sizes[1];  // 50000

    const int threads = 256;   // 8 warps = 8 nodes per block
    const int blocks  = (B * 32 + threads - 1) / threads;
    gcn_agg_kernel<<<blocks, threads>>>(feat, nodes, neigh, out, B);
}

// round 11
// speedup vs baseline: 1.0576x; 1.0506x over previous
#include <cuda_runtime.h>
#include <cuda_bf16.h>
#include <stdint.h>

// GCN mean aggregation (converged — at the L2 random-gather bandwidth wall):
//   out[i, :] = mean over {nodes[i]} ∪ neigh_idx[i,0..31] of features[idx, :]
// features [V=100000, D=128] f32, nodes [B] int{32|64}, neigh [B,32] int{32|64}.
//
// Design validated over 8 structural variants (all 47.6-52us):
//  - warp per node; lane loads 4B -> each LDG touches exactly one 128B line,
//    4 loads per 512B feature row, fully coalesced
//  - feature loads: .nc + L2::evict_last policy (THE win, 80.9 -> 47.6us:
//    keeps the 51.2MB table resident against write-once stream eviction)
//  - index loads / output stores: streaming (.cs)
//  - indices fetched coalesced (lane j = neighbor j) + shfl broadcast
//  - index dtype (int64 vs JAX-demoted int32) probed inline: little-endian
//    int64 values < 2^31 have every odd 32-bit word zero
// R11 refinements: 512-thread blocks (halve block-wave transitions) and a
// single-load dtype probe per warp (16 lanes x v2 covers 64 words).

static constexpr int KN = 32;
static constexpr float INV_CNT = 1.0f / 33.0f;

__device__ __forceinline__ uint64_t make_keep_policy() {
    uint64_t pol;
    asm("createpolicy.fractional.L2::evict_last.b64 %0, 1.0;" : "=l"(pol));
    return pol;
}

__device__ __forceinline__ float ldg_keep1(const float* p, uint64_t pol) {
    float v;
    asm volatile("ld.global.nc.L2::cache_hint.f32 %0, [%1], %2;"
                 : "=f"(v) : "l"(p), "l"(pol));
    return v;
}

__device__ __forceinline__ void stg_stream1(float* p, float v) {
    asm volatile("st.global.cs.f32 [%0], %1;" :: "l"(p), "f"(v) : "memory");
}

__device__ __forceinline__ int2 ldg_cs32x2(const int* p) {
    int2 v;
    asm volatile("ld.global.cs.v2.s32 {%0,%1}, [%2];"
                 : "=r"(v.x), "=r"(v.y) : "l"(p));
    return v;
}

__device__ __forceinline__ long long ldg_cs64(const long long* p) {
    long long v;
    asm volatile("ld.global.cs.s64 %0, [%1];" : "=l"(v) : "l"(p));
    return v;
}

__device__ __forceinline__ int ldg_cs32(const int* p) {
    int v;
    asm volatile("ld.global.cs.s32 %0, [%1];" : "=r"(v) : "l"(p));
    return v;
}

__global__ __launch_bounds__(512) void gcn_agg_kernel(
    const float* __restrict__ feat,
    const void*  __restrict__ nodes,
    const void*  __restrict__ neigh,
    float*       __restrict__ out,
    int B)
{
    const int node = (blockIdx.x * blockDim.x + threadIdx.x) >> 5;
    const int lane = threadIdx.x & 31;
    if (node >= B) return;

    // Inline dtype probe: lanes 0-15 cover the first 64 int32 words of neigh
    // with one v2 load each; odd words all zero <=> little-endian int64.
    int odd_ok = 1;
    if (lane < 16) {
        const int2 probe = ldg_cs32x2((const int*)neigh + 2 * lane);
        odd_ok = (probe.y == 0);
    }
    const bool is64 = (__ballot_sync(0xffffffffu, odd_ok) == 0xffffffffu);

    // Fetch this node's indices: lane j holds neighbor j (coalesced).
    int my_idx, self_idx;
    if (is64) {
        my_idx   = (int)ldg_cs64((const long long*)neigh + (long long)node * KN + lane);
        self_idx = (int)ldg_cs64((const long long*)nodes + node);
    } else {
        my_idx   = ldg_cs32((const int*)neigh + (long long)node * KN + lane);
        self_idx = ldg_cs32((const int*)nodes + node);
    }

    const uint64_t pol = make_keep_policy();

    // Gather: 4 single-line LDG.32 per 512B row.
    float acc0, acc1, acc2, acc3;
    {
        const float* r = feat + (long long)self_idx * 128 + lane;
        acc0 = ldg_keep1(r,      pol);
        acc1 = ldg_keep1(r + 32, pol);
        acc2 = ldg_keep1(r + 64, pol);
        acc3 = ldg_keep1(r + 96, pol);
    }
#pragma unroll
    for (int j = 0; j < KN; j++) {
        const int idx = __shfl_sync(0xffffffffu, my_idx, j);
        const float* r = feat + (long long)idx * 128 + lane;
        acc0 += ldg_keep1(r,      pol);
        acc1 += ldg_keep1(r + 32, pol);
        acc2 += ldg_keep1(r + 64, pol);
        acc3 += ldg_keep1(r + 96, pol);
    }

    float* op = out + (long long)node * 128 + lane;
    stg_stream1(op,      acc0 * INV_CNT);
    stg_stream1(op + 32, acc1 * INV_CNT);
    stg_stream1(op + 64, acc2 * INV_CNT);
    stg_stream1(op + 96, acc3 * INV_CNT);
}

extern "C" void kernel_launch(void* const* d_in, const int* in_sizes, int n_in,
                              void* d_out, int out_size) {
    const float* feat  = (const float*)d_in[0];
    const void*  nodes = d_in[1];
    const void*  neigh = d_in[2];
    float*       out   = (float*)d_out;

    const int B = in_sizes[1];  // 50000

    const int threads = 512;   // 16 warps = 16 nodes per block
    const int blocks  = (B * 32 + threads - 1) / threads;
    gcn_agg_kernel<<<blocks, threads>>>(feat, nodes, neigh, out, B);
}